// round 12
// baseline (speedup 1.0000x reference)
#include <cuda_runtime.h>
#include <cuda_bf16.h>
#include <cstdint>

#define NB 8
#define NH 16
#define SEQ 1024
#define DDIM 64
#define BM 64
#define BN 64
#define NTH 256
#define LOG2E 1.4426950408889634f

// SMEM: Q hi/lo (16KB) + 2 double-buffered K/V bf16 tile sets (32KB each)
#define SQH 0
#define SQL 8192
#define SBUF 16384
#define KVSTRIDE 32768
// within a KV buffer: KH +0, KL +8192, VH +16384, VL +24576
#define SMTOT (SBUF + 2 * KVSTRIDE)   // 81920

__device__ __forceinline__ uint32_t smem_u32(const void* p) {
    uint32_t a;
    asm("{ .reg .u64 t; cvta.to.shared.u64 t, %1; cvt.u32.u64 %0, t; }" : "=r"(a) : "l"(p));
    return a;
}
__device__ __forceinline__ uint32_t sw(uint32_t o) { return o ^ ((o >> 3) & 0x70); }

__device__ __forceinline__ void ldsm4(uint32_t& r0, uint32_t& r1, uint32_t& r2, uint32_t& r3,
                                      uint32_t a) {
    asm volatile("ldmatrix.sync.aligned.m8n8.x4.shared.b16 {%0,%1,%2,%3},[%4];"
                 : "=r"(r0), "=r"(r1), "=r"(r2), "=r"(r3) : "r"(a));
}
__device__ __forceinline__ void ldsm4t(uint32_t& r0, uint32_t& r1, uint32_t& r2, uint32_t& r3,
                                       uint32_t a) {
    asm volatile("ldmatrix.sync.aligned.m8n8.x4.trans.shared.b16 {%0,%1,%2,%3},[%4];"
                 : "=r"(r0), "=r"(r1), "=r"(r2), "=r"(r3) : "r"(a));
}
__device__ __forceinline__ void mma16816(float* c, uint32_t a0, uint32_t a1, uint32_t a2,
                                         uint32_t a3, uint32_t b0, uint32_t b1) {
    asm volatile("mma.sync.aligned.m16n8k16.row.col.f32.bf16.bf16.f32 "
                 "{%0,%1,%2,%3},{%4,%5,%6,%7},{%8,%9},{%0,%1,%2,%3};"
                 : "+f"(c[0]), "+f"(c[1]), "+f"(c[2]), "+f"(c[3])
                 : "r"(a0), "r"(a1), "r"(a2), "r"(a3), "r"(b0), "r"(b1));
}
// pack (x0,x1) -> bf16x2 hi part + bf16x2 residual part
__device__ __forceinline__ void split2(float x0, float x1, uint32_t& hi, uint32_t& lo) {
    uint32_t hh;
    asm("cvt.rn.bf16x2.f32 %0, %1, %2;" : "=r"(hh) : "f"(x1), "f"(x0));
    float h0 = __uint_as_float(hh << 16);
    float h1 = __uint_as_float(hh & 0xffff0000u);
    float l0 = x0 - h0, l1 = x1 - h1;
    uint32_t ll;
    asm("cvt.rn.bf16x2.f32 %0, %1, %2;" : "=r"(ll) : "f"(l1), "f"(l0));
    hi = hh; lo = ll;
}

__global__ __launch_bounds__(NTH, 2)
void attn_mma(const float* __restrict__ q, const float* __restrict__ k,
              const float* __restrict__ v, const int* __restrict__ mask,
              const float* __restrict__ bias, float* __restrict__ out)
{
    extern __shared__ char smem[];
    __shared__ int s_len;
    __shared__ float s_li[64];
    const int tid  = threadIdx.x;
    const int lane = tid & 31;
    const int w    = tid >> 5;
    const int w_m  = w & 3;        // row group: rows 16*w_m .. +15
    const int w_n  = w >> 2;       // key half: keys 32*w_n .. +31 of each tile
    const int nh   = 32 * w_n;
    const int rowg = 16 * w_m;
    const int m0   = blockIdx.x * BM;
    const int h    = blockIdx.y;
    const int b    = blockIdx.z;
    const int bh   = b * NH + h;
    const uint32_t sb = smem_u32(smem);

    if (tid == 0) s_len = 0;
    __syncthreads();
    {   // valid length (mask int32 0/1, monotone prefix)
        const int* mb = mask + (size_t)b * SEQ;
        int part = 0;
        for (int i = tid; i < SEQ; i += NTH) part += (mb[i] != 0);
        #pragma unroll
        for (int o = 16; o > 0; o >>= 1) part += __shfl_xor_sync(0xffffffffu, part, o);
        if (lane == 0) atomicAdd(&s_len, part);
    }

    // per-thread K/V conversion slice: this half (128 threads) owns its 32 rows;
    // 4 threads per row, 16 floats (cols cf..cf+15) each.
    const int g  = tid & 127;                 // id within the 128-thread half
    const int kr = nh + (g >> 2);             // tile row (nh..nh+31)
    const int cf = (g & 3) * 16;              // float col base
    const uint32_t kvbase = (uint32_t)kr * 128 + (uint32_t)cf * 2;   // byte base
    const uint32_t so0 = sw(kvbase);
    const uint32_t so1 = sw(kvbase + 16);
    const float* kbp = k + (((size_t)bh) * SEQ + kr) * DDIM + cf;
    const float* vbp = v + (((size_t)bh) * SEQ + kr) * DDIM + cf;

    // ---- prologue: prefetch tile-0 K and V fp32 into registers ----
    float4 pk[4], pv[4];
    #pragma unroll
    for (int i = 0; i < 4; i++) {
        pk[i] = *(const float4*)(kbp + 4 * i);
        pv[i] = *(const float4*)(vbp + 4 * i);
    }

    // ---- Q tile fp32 -> bf16 hi/lo, swizzled [row][d] 128B rows ----
    {
        const int row  = tid >> 2;                 // 0..63
        const int colf = (tid & 3) * 16;           // float col base
        const float* qrow = q + (((size_t)bh) * SEQ + m0 + row) * DDIM + colf;
        #pragma unroll
        for (int c = 0; c < 2; c++) {              // 2 chunks of 8 floats
            float4 t0 = *(const float4*)(qrow + 8 * c);
            float4 t1 = *(const float4*)(qrow + 8 * c + 4);
            uint4 hv, lv;
            split2(t0.x, t0.y, hv.x, lv.x);
            split2(t0.z, t0.w, hv.y, lv.y);
            split2(t1.x, t1.y, hv.z, lv.z);
            split2(t1.z, t1.w, hv.w, lv.w);
            uint32_t off = sw(row * 128 + colf * 2 + 16 * c);
            *(uint4*)(smem + SQH + off) = hv;
            *(uint4*)(smem + SQL + off) = lv;
        }
    }
    __syncthreads();
    const int len = s_len;
    const int n_tiles = (len + BN - 1) / BN;

    // ldmatrix per-lane addressing pattern
    const int r8  = (lane & 7) + ((lane >> 3) & 1) * 8;
    const int c16 = ((lane >> 4) & 1) * 16;

    float o[8][4];
    #pragma unroll
    for (int i = 0; i < 8; i++)
        #pragma unroll
        for (int j = 0; j < 4; j++) o[i][j] = 0.0f;
    float li1 = 0.0f, li2 = 0.0f;

    const float* bp1 = bias + ((size_t)h * SEQ + (m0 + rowg + (lane >> 2))) * SEQ;
    const float* bp2 = bp1 + 8 * SEQ;

    for (int t = 0; t < n_tiles; t++) {
        const int n0 = t * BN;
        char* bufp = smem + SBUF + (size_t)(t & 1) * KVSTRIDE;
        const uint32_t kvb = sb + SBUF + (uint32_t)(t & 1) * KVSTRIDE;

        // ---- convert prefetched K regs -> bf16 hi/lo in smem ----
        #pragma unroll
        for (int c = 0; c < 2; c++) {
            uint4 hv, lv;
            split2(pk[2 * c].x,     pk[2 * c].y,     hv.x, lv.x);
            split2(pk[2 * c].z,     pk[2 * c].w,     hv.y, lv.y);
            split2(pk[2 * c + 1].x, pk[2 * c + 1].y, hv.z, lv.z);
            split2(pk[2 * c + 1].z, pk[2 * c + 1].w, hv.w, lv.w);
            uint32_t off = c ? so1 : so0;
            *(uint4*)(bufp + 0    + off) = hv;
            *(uint4*)(bufp + 8192 + off) = lv;
        }
        // K ready for this half
        asm volatile("bar.sync %0, 128;" :: "r"(1 + w_n) : "memory");

        // ---- prefetch next tile's K (consumed at top of t+1) ----
        if (t + 1 < n_tiles) {
            const float* krow = kbp + (size_t)(t + 1) * BN * DDIM;
            #pragma unroll
            for (int i = 0; i < 4; i++) pk[i] = *(const float4*)(krow + 4 * i);
        }

        // ---- bias prefetch (pre-scaled by log2(e); overlaps GEMM1) ----
        float2 bb1[4], bb2[4];
        #pragma unroll
        for (int nb = 0; nb < 4; nb++) {
            int c = n0 + nh + 8 * nb + (lane & 3) * 2;
            bb1[nb] = *(const float2*)(bp1 + c);
            bb2[nb] = *(const float2*)(bp2 + c);
            bb1[nb].x *= LOG2E; bb1[nb].y *= LOG2E;
            bb2[nb].x *= LOG2E; bb2[nb].y *= LOG2E;
        }

        // ---- GEMM1: S = QK^T over this warp's 32-key half, 3-way split ----
        float s[4][4];
        #pragma unroll
        for (int i = 0; i < 4; i++)
            #pragma unroll
            for (int j = 0; j < 4; j++) s[i][j] = 0.0f;
        #pragma unroll
        for (int kbk = 0; kbk < 4; kbk++) {
            uint32_t qoff = sw((rowg + r8) * 128 + 32 * kbk + c16);
            uint32_t a0, a1, a2, a3, e0, e1, e2, e3;
            ldsm4(a0, a1, a2, a3, sb + SQH + qoff);
            ldsm4(e0, e1, e2, e3, sb + SQL + qoff);
            #pragma unroll
            for (int nbp = 0; nbp < 2; nbp++) {
                uint32_t boff = sw((nh + 16 * nbp + r8) * 128 + 32 * kbk + c16);
                uint32_t bh0, bh1, bh2, bh3, bl0, bl1, bl2, bl3;
                ldsm4(bh0, bh1, bh2, bh3, kvb + boff);
                ldsm4(bl0, bl1, bl2, bl3, kvb + 8192 + boff);
                mma16816(s[2 * nbp],     a0, a1, a2, a3, bh0, bh2);
                mma16816(s[2 * nbp + 1], a0, a1, a2, a3, bh1, bh3);
                mma16816(s[2 * nbp],     e0, e1, e2, e3, bh0, bh2);
                mma16816(s[2 * nbp + 1], e0, e1, e2, e3, bh1, bh3);
                mma16816(s[2 * nbp],     a0, a1, a2, a3, bl0, bl2);
                mma16816(s[2 * nbp + 1], a0, a1, a2, a3, bl1, bl3);
            }
        }

        // ---- softmax: p = exp2(s*log2e + bias*log2e), no max-sub ----
        uint32_t pah[2][4], pal[2][4];
        #pragma unroll
        for (int nb = 0; nb < 4; nb++) {
            int n = n0 + nh + 8 * nb + (lane & 3) * 2;
            float p0 = (n     < len) ? exp2f(fmaf(s[nb][0], LOG2E, bb1[nb].x)) : 0.0f;
            float p1 = (n + 1 < len) ? exp2f(fmaf(s[nb][1], LOG2E, bb1[nb].y)) : 0.0f;
            float p2 = (n     < len) ? exp2f(fmaf(s[nb][2], LOG2E, bb2[nb].x)) : 0.0f;
            float p3 = (n + 1 < len) ? exp2f(fmaf(s[nb][3], LOG2E, bb2[nb].y)) : 0.0f;
            li1 += p0 + p1;
            li2 += p2 + p3;
            split2(p0, p1, pah[nb >> 1][(nb & 1) * 2],     pal[nb >> 1][(nb & 1) * 2]);
            split2(p2, p3, pah[nb >> 1][(nb & 1) * 2 + 1], pal[nb >> 1][(nb & 1) * 2 + 1]);
        }

        // ---- convert prefetched V regs -> bf16 hi/lo in smem ----
        #pragma unroll
        for (int c = 0; c < 2; c++) {
            uint4 hv, lv;
            split2(pv[2 * c].x,     pv[2 * c].y,     hv.x, lv.x);
            split2(pv[2 * c].z,     pv[2 * c].w,     hv.y, lv.y);
            split2(pv[2 * c + 1].x, pv[2 * c + 1].y, hv.z, lv.z);
            split2(pv[2 * c + 1].z, pv[2 * c + 1].w, hv.w, lv.w);
            uint32_t off = c ? so1 : so0;
            *(uint4*)(bufp + 16384 + off) = hv;
            *(uint4*)(bufp + 24576 + off) = lv;
        }
        // V ready for this half
        asm volatile("bar.sync %0, 128;" :: "r"(3 + w_n) : "memory");

        // ---- prefetch next tile's V (consumed mid-tile t+1) ----
        if (t + 1 < n_tiles) {
            const float* vrow = vbp + (size_t)(t + 1) * BN * DDIM;
            #pragma unroll
            for (int i = 0; i < 4; i++) pv[i] = *(const float4*)(vrow + 4 * i);
        }

        // ---- GEMM2: O(partial) += P V over this warp's 32 keys ----
        const uint32_t vh_ = kvb + 16384;
        const uint32_t vl_ = kvb + 24576;
        #pragma unroll
        for (int kk = 0; kk < 2; kk++) {
            #pragma unroll
            for (int nbp = 0; nbp < 4; nbp++) {
                uint32_t voff = sw((nh + 16 * kk + r8) * 128 + 32 * nbp + c16);
                uint32_t vh0, vh1, vh2, vh3, vl0, vl1, vl2, vl3;
                ldsm4t(vh0, vh1, vh2, vh3, vh_ + voff);
                ldsm4t(vl0, vl1, vl2, vl3, vl_ + voff);
                mma16816(o[2 * nbp],     pah[kk][0], pah[kk][1], pah[kk][2], pah[kk][3], vh0, vh1);
                mma16816(o[2 * nbp + 1], pah[kk][0], pah[kk][1], pah[kk][2], pah[kk][3], vh2, vh3);
                mma16816(o[2 * nbp],     pal[kk][0], pal[kk][1], pal[kk][2], pal[kk][3], vh0, vh1);
                mma16816(o[2 * nbp + 1], pal[kk][0], pal[kk][1], pal[kk][2], pal[kk][3], vh2, vh3);
                mma16816(o[2 * nbp],     pah[kk][0], pah[kk][1], pah[kk][2], pah[kk][3], vl0, vl1);
                mma16816(o[2 * nbp + 1], pah[kk][0], pah[kk][1], pah[kk][2], pah[kk][3], vl2, vl3);
            }
        }
    }

    // ---- reduce li across the quad (lanes l^1, l^2 hold the same rows) ----
    li1 += __shfl_xor_sync(0xffffffffu, li1, 1);
    li1 += __shfl_xor_sync(0xffffffffu, li1, 2);
    li2 += __shfl_xor_sync(0xffffffffu, li2, 1);
    li2 += __shfl_xor_sync(0xffffffffu, li2, 2);

    // ---- combine the two key-halves: O(partial) and li through smem ----
    __syncthreads();   // all GEMM2 smem reads done; safe to alias KV buffer 0
    float* oshare = (float*)(smem + SBUF);   // [64][64] fp32 = 16KB
    const int r1 = rowg + (lane >> 2);
    if (w_n == 1) {
        #pragma unroll
        for (int nb = 0; nb < 8; nb++) {
            int c = 8 * nb + (lane & 3) * 2;
            *(float2*)(oshare + r1 * 64 + c)       = make_float2(o[nb][0], o[nb][1]);
            *(float2*)(oshare + (r1 + 8) * 64 + c) = make_float2(o[nb][2], o[nb][3]);
        }
        if ((lane & 3) == 0) {
            s_li[r1]     = li1;
            s_li[r1 + 8] = li2;
        }
    }
    __syncthreads();

    if (w_n == 0) {
        const float lt1 = li1 + s_li[r1];
        const float lt2 = li2 + s_li[r1 + 8];
        const float inv1 = ((m0 + r1)     < len) ? (1.0f / lt1) : 0.0f;
        const float inv2 = ((m0 + r1 + 8) < len) ? (1.0f / lt2) : 0.0f;
        float* o1 = out + ((size_t)b * SEQ + m0 + r1) * (NH * DDIM) + (size_t)h * DDIM;
        float* o2 = o1 + 8 * (NH * DDIM);
        #pragma unroll
        for (int nb = 0; nb < 8; nb++) {
            int c = 8 * nb + (lane & 3) * 2;
            float2 q1 = *(const float2*)(oshare + r1 * 64 + c);
            float2 q2 = *(const float2*)(oshare + (r1 + 8) * 64 + c);
            float2 w1 = {(o[nb][0] + q1.x) * inv1, (o[nb][1] + q1.y) * inv1};
            float2 w2 = {(o[nb][2] + q2.x) * inv2, (o[nb][3] + q2.y) * inv2};
            *(float2*)(o1 + c) = w1;
            *(float2*)(o2 + c) = w2;
        }
    }
}

extern "C" void kernel_launch(void* const* d_in, const int* in_sizes, int n_in,
                              void* d_out, int out_size)
{
    const float* q    = (const float*)d_in[0];
    const float* k    = (const float*)d_in[1];
    const float* v    = (const float*)d_in[2];
    const int*   mask = (const int*)d_in[3];
    const float* bias = (const float*)d_in[4];
    float* out = (float*)d_out;

    cudaFuncSetAttribute(attn_mma, cudaFuncAttributeMaxDynamicSharedMemorySize, SMTOT);
    dim3 grid(SEQ / BM, NH, NB);
    attn_mma<<<grid, NTH, SMTOT>>>(q, k, v, mask, bias, out);
}

// round 13
// speedup vs baseline: 1.0043x; 1.0043x over previous
#include <cuda_runtime.h>
#include <cuda_bf16.h>
#include <cstdint>

#define NB 8
#define NH 16
#define SEQ 1024
#define DDIM 64
#define BM 64
#define BN 64
#define NTH 256
#define LOG2E 1.4426950408889634f

// SMEM (64KB/CTA -> 3 CTAs/SM):
//   Q hi/lo 16KB, K double-buffered 2x16KB (KH+KL), V single 16KB (VH+VL)
#define SQH 0
#define SQL 8192
#define SKBUF 16384
#define KSTRIDE 16384
#define SVH 49152
#define SVL 57344
#define SMTOT 65536

#define KVELEMS (NB * NH * SEQ * DDIM)   // 8,388,608

// pre-converted K/V in bf16 hi/lo, [b,h,n,d] row-major
__device__ __nv_bfloat16 g_khi[KVELEMS];
__device__ __nv_bfloat16 g_klo[KVELEMS];
__device__ __nv_bfloat16 g_vhi[KVELEMS];
__device__ __nv_bfloat16 g_vlo[KVELEMS];

__device__ __forceinline__ uint32_t smem_u32(const void* p) {
    uint32_t a;
    asm("{ .reg .u64 t; cvta.to.shared.u64 t, %1; cvt.u32.u64 %0, t; }" : "=r"(a) : "l"(p));
    return a;
}
__device__ __forceinline__ uint32_t sw(uint32_t o) { return o ^ ((o >> 3) & 0x70); }

__device__ __forceinline__ void ldsm4(uint32_t& r0, uint32_t& r1, uint32_t& r2, uint32_t& r3,
                                      uint32_t a) {
    asm volatile("ldmatrix.sync.aligned.m8n8.x4.shared.b16 {%0,%1,%2,%3},[%4];"
                 : "=r"(r0), "=r"(r1), "=r"(r2), "=r"(r3) : "r"(a));
}
__device__ __forceinline__ void ldsm4t(uint32_t& r0, uint32_t& r1, uint32_t& r2, uint32_t& r3,
                                       uint32_t a) {
    asm volatile("ldmatrix.sync.aligned.m8n8.x4.trans.shared.b16 {%0,%1,%2,%3},[%4];"
                 : "=r"(r0), "=r"(r1), "=r"(r2), "=r"(r3) : "r"(a));
}
__device__ __forceinline__ void mma16816(float* c, uint32_t a0, uint32_t a1, uint32_t a2,
                                         uint32_t a3, uint32_t b0, uint32_t b1) {
    asm volatile("mma.sync.aligned.m16n8k16.row.col.f32.bf16.bf16.f32 "
                 "{%0,%1,%2,%3},{%4,%5,%6,%7},{%8,%9},{%0,%1,%2,%3};"
                 : "+f"(c[0]), "+f"(c[1]), "+f"(c[2]), "+f"(c[3])
                 : "r"(a0), "r"(a1), "r"(a2), "r"(a3), "r"(b0), "r"(b1));
}
// pack (x0,x1) -> bf16x2 hi part + bf16x2 residual part
__device__ __forceinline__ void split2(float x0, float x1, uint32_t& hi, uint32_t& lo) {
    uint32_t hh;
    asm("cvt.rn.bf16x2.f32 %0, %1, %2;" : "=r"(hh) : "f"(x1), "f"(x0));
    float h0 = __uint_as_float(hh << 16);
    float h1 = __uint_as_float(hh & 0xffff0000u);
    float l0 = x0 - h0, l1 = x1 - h1;
    uint32_t ll;
    asm("cvt.rn.bf16x2.f32 %0, %1, %2;" : "=r"(ll) : "f"(l1), "f"(l0));
    hi = hh; lo = ll;
}
__device__ __forceinline__ void cpasync16(uint32_t dst, const void* src) {
    asm volatile("cp.async.cg.shared.global [%0], [%1], 16;" :: "r"(dst), "l"(src));
}

// ---- prepass: convert K,V fp32 -> bf16 hi/lo, once for the whole problem ----
__global__ __launch_bounds__(256)
void conv_kv(const float4* __restrict__ k4, const float4* __restrict__ v4)
{
    const int i = blockIdx.x * 256 + threadIdx.x;   // one float4 (4 elems) each
    float4 a = k4[i];
    uint2 hi, lo;
    split2(a.x, a.y, hi.x, lo.x);
    split2(a.z, a.w, hi.y, lo.y);
    ((uint2*)g_khi)[i] = hi;
    ((uint2*)g_klo)[i] = lo;
    float4 b = v4[i];
    split2(b.x, b.y, hi.x, lo.x);
    split2(b.z, b.w, hi.y, lo.y);
    ((uint2*)g_vhi)[i] = hi;
    ((uint2*)g_vlo)[i] = lo;
}

__global__ __launch_bounds__(NTH, 3)
void attn_mma(const float* __restrict__ q, const int* __restrict__ mask,
              const float* __restrict__ bias, float* __restrict__ out)
{
    extern __shared__ char smem[];
    __shared__ int s_len;
    __shared__ float s_li[64];
    const int tid  = threadIdx.x;
    const int lane = tid & 31;
    const int w    = tid >> 5;
    const int w_m  = w & 3;        // row group: rows 16*w_m .. +15
    const int w_n  = w >> 2;       // key half: keys 32*w_n .. +31 of each tile
    const int nh   = 32 * w_n;
    const int rowg = 16 * w_m;
    const int m0   = blockIdx.x * BM;
    const int h    = blockIdx.y;
    const int b    = blockIdx.z;
    const int bh   = b * NH + h;
    const uint32_t sb = smem_u32(smem);

    // per-thread cp.async slice: this half (128 threads) loads its own 32 rows;
    // 4 threads per row, two 16B chunks per array.
    const int g    = tid & 127;                // id within the 128-thread half
    const int kr   = nh + (g >> 2);            // tile row (nh..nh+31)
    const int cc   = (g & 3) * 16;             // elem col base
    const uint32_t off0 = sw((uint32_t)kr * 128 + (uint32_t)cc * 2);
    const uint32_t off1 = sw((uint32_t)kr * 128 + (uint32_t)cc * 2 + 16);
    const size_t   gsrc0 = ((size_t)bh * SEQ + kr) * DDIM + cc;

    // ---- prologue: issue K(0) and V(0) as separate cp.async groups ----
    {
        const uint32_t dk = sb + SKBUF;
        cpasync16(dk + off0,         g_khi + gsrc0);
        cpasync16(dk + off1,         g_khi + gsrc0 + 8);
        cpasync16(dk + 8192 + off0,  g_klo + gsrc0);
        cpasync16(dk + 8192 + off1,  g_klo + gsrc0 + 8);
        asm volatile("cp.async.commit_group;" ::: "memory");
        cpasync16(sb + SVH + off0,   g_vhi + gsrc0);
        cpasync16(sb + SVH + off1,   g_vhi + gsrc0 + 8);
        cpasync16(sb + SVL + off0,   g_vlo + gsrc0);
        cpasync16(sb + SVL + off1,   g_vlo + gsrc0 + 8);
        asm volatile("cp.async.commit_group;" ::: "memory");
    }

    if (tid == 0) s_len = 0;
    __syncthreads();
    {   // valid length (mask int32 0/1, monotone prefix)
        const int* mb = mask + (size_t)b * SEQ;
        int part = 0;
        for (int i = tid; i < SEQ; i += NTH) part += (mb[i] != 0);
        #pragma unroll
        for (int o = 16; o > 0; o >>= 1) part += __shfl_xor_sync(0xffffffffu, part, o);
        if (lane == 0) atomicAdd(&s_len, part);
    }

    // ---- Q tile fp32 -> bf16 hi/lo, swizzled [row][d] 128B rows ----
    {
        const int row  = tid >> 2;                 // 0..63
        const int colf = (tid & 3) * 16;           // float col base
        const float* qrow = q + (((size_t)bh) * SEQ + m0 + row) * DDIM + colf;
        #pragma unroll
        for (int c = 0; c < 2; c++) {              // 2 chunks of 8 floats
            float4 t0 = *(const float4*)(qrow + 8 * c);
            float4 t1 = *(const float4*)(qrow + 8 * c + 4);
            uint4 hv, lv;
            split2(t0.x, t0.y, hv.x, lv.x);
            split2(t0.z, t0.w, hv.y, lv.y);
            split2(t1.x, t1.y, hv.z, lv.z);
            split2(t1.z, t1.w, hv.w, lv.w);
            uint32_t off = sw(row * 128 + colf * 2 + 16 * c);
            *(uint4*)(smem + SQH + off) = hv;
            *(uint4*)(smem + SQL + off) = lv;
        }
    }
    __syncthreads();
    const int len = s_len;
    const int n_tiles = (len + BN - 1) / BN;

    // ldmatrix per-lane addressing pattern
    const int r8  = (lane & 7) + ((lane >> 3) & 1) * 8;
    const int c16 = ((lane >> 4) & 1) * 16;

    float o[8][4];
    #pragma unroll
    for (int i = 0; i < 8; i++)
        #pragma unroll
        for (int j = 0; j < 4; j++) o[i][j] = 0.0f;
    float li1 = 0.0f, li2 = 0.0f;

    const float* bp1 = bias + ((size_t)h * SEQ + (m0 + rowg + (lane >> 2))) * SEQ;
    const float* bp2 = bp1 + 8 * SEQ;

    for (int t = 0; t < n_tiles; t++) {
        const int n0 = t * BN;
        const uint32_t kvbK = sb + SKBUF + (uint32_t)(t & 1) * KSTRIDE;

        // ---- bias prefetch (pre-scaled by log2(e); overlaps the wait) ----
        float2 bb1[4], bb2[4];
        #pragma unroll
        for (int nb = 0; nb < 4; nb++) {
            int c = n0 + nh + 8 * nb + (lane & 3) * 2;
            bb1[nb] = *(const float2*)(bp1 + c);
            bb2[nb] = *(const float2*)(bp2 + c);
            bb1[nb].x *= LOG2E; bb1[nb].y *= LOG2E;
            bb2[nb].x *= LOG2E; bb2[nb].y *= LOG2E;
        }

        // ---- K(t) must be resident (allow 1 newer group = V(t) to pend) ----
        asm volatile("cp.async.wait_group 1;" ::: "memory");
        asm volatile("bar.sync %0, 128;" :: "r"(1 + w_n) : "memory");

        // ---- issue K(t+1) into the other K buffer (WAR-safe: reads of that
        //      buffer were in GEMM1(t-1), before this half's barrier above) ----
        if (t + 1 < n_tiles) {
            const uint32_t dk = sb + SKBUF + (uint32_t)((t + 1) & 1) * KSTRIDE;
            const size_t src = gsrc0 + (size_t)(t + 1) * BN * DDIM;
            cpasync16(dk + off0,        g_khi + src);
            cpasync16(dk + off1,        g_khi + src + 8);
            cpasync16(dk + 8192 + off0, g_klo + src);
            cpasync16(dk + 8192 + off1, g_klo + src + 8);
        }
        asm volatile("cp.async.commit_group;" ::: "memory");

        // ---- GEMM1: S = QK^T over this warp's 32-key half, 3-way split ----
        float s[4][4];
        #pragma unroll
        for (int i = 0; i < 4; i++)
            #pragma unroll
            for (int j = 0; j < 4; j++) s[i][j] = 0.0f;
        #pragma unroll
        for (int kbk = 0; kbk < 4; kbk++) {
            uint32_t qoff = sw((rowg + r8) * 128 + 32 * kbk + c16);
            uint32_t a0, a1, a2, a3, e0, e1, e2, e3;
            ldsm4(a0, a1, a2, a3, sb + SQH + qoff);
            ldsm4(e0, e1, e2, e3, sb + SQL + qoff);
            #pragma unroll
            for (int nbp = 0; nbp < 2; nbp++) {
                uint32_t boff = sw((nh + 16 * nbp + r8) * 128 + 32 * kbk + c16);
                uint32_t bh0, bh1, bh2, bh3, bl0, bl1, bl2, bl3;
                ldsm4(bh0, bh1, bh2, bh3, kvbK + boff);
                ldsm4(bl0, bl1, bl2, bl3, kvbK + 8192 + boff);
                mma16816(s[2 * nbp],     a0, a1, a2, a3, bh0, bh2);
                mma16816(s[2 * nbp + 1], a0, a1, a2, a3, bh1, bh3);
                mma16816(s[2 * nbp],     e0, e1, e2, e3, bh0, bh2);
                mma16816(s[2 * nbp + 1], e0, e1, e2, e3, bh1, bh3);
                mma16816(s[2 * nbp],     a0, a1, a2, a3, bl0, bl2);
                mma16816(s[2 * nbp + 1], a0, a1, a2, a3, bl1, bl3);
            }
        }

        // ---- softmax: p = exp2(s*log2e + bias*log2e), no max-sub ----
        uint32_t pah[2][4], pal[2][4];
        #pragma unroll
        for (int nb = 0; nb < 4; nb++) {
            int n = n0 + nh + 8 * nb + (lane & 3) * 2;
            float p0 = (n     < len) ? exp2f(fmaf(s[nb][0], LOG2E, bb1[nb].x)) : 0.0f;
            float p1 = (n + 1 < len) ? exp2f(fmaf(s[nb][1], LOG2E, bb1[nb].y)) : 0.0f;
            float p2 = (n     < len) ? exp2f(fmaf(s[nb][2], LOG2E, bb2[nb].x)) : 0.0f;
            float p3 = (n + 1 < len) ? exp2f(fmaf(s[nb][3], LOG2E, bb2[nb].y)) : 0.0f;
            li1 += p0 + p1;
            li2 += p2 + p3;
            split2(p0, p1, pah[nb >> 1][(nb & 1) * 2],     pal[nb >> 1][(nb & 1) * 2]);
            split2(p2, p3, pah[nb >> 1][(nb & 1) * 2 + 1], pal[nb >> 1][(nb & 1) * 2 + 1]);
        }

        // ---- V(t) must be resident (allow 1 newer group = K(t+1) to pend) ----
        asm volatile("cp.async.wait_group 1;" ::: "memory");
        asm volatile("bar.sync %0, 128;" :: "r"(3 + w_n) : "memory");

        // ---- GEMM2: O(partial) += P V over this warp's 32 keys ----
        #pragma unroll
        for (int kk = 0; kk < 2; kk++) {
            #pragma unroll
            for (int nbp = 0; nbp < 4; nbp++) {
                uint32_t voff = sw((nh + 16 * kk + r8) * 128 + 32 * nbp + c16);
                uint32_t vh0, vh1, vh2, vh3, vl0, vl1, vl2, vl3;
                ldsm4t(vh0, vh1, vh2, vh3, sb + SVH + voff);
                ldsm4t(vl0, vl1, vl2, vl3, sb + SVL + voff);
                mma16816(o[2 * nbp],     pah[kk][0], pah[kk][1], pah[kk][2], pah[kk][3], vh0, vh1);
                mma16816(o[2 * nbp + 1], pah[kk][0], pah[kk][1], pah[kk][2], pah[kk][3], vh2, vh3);
                mma16816(o[2 * nbp],     pal[kk][0], pal[kk][1], pal[kk][2], pal[kk][3], vh0, vh1);
                mma16816(o[2 * nbp + 1], pal[kk][0], pal[kk][1], pal[kk][2], pal[kk][3], vh2, vh3);
                mma16816(o[2 * nbp],     pah[kk][0], pah[kk][1], pah[kk][2], pah[kk][3], vl0, vl1);
                mma16816(o[2 * nbp + 1], pah[kk][0], pah[kk][1], pah[kk][2], pah[kk][3], vl2, vl3);
            }
        }

        // ---- all half-warps done reading V(t); safe to overwrite V buffer ----
        asm volatile("bar.sync %0, 128;" :: "r"(5 + w_n) : "memory");
        if (t + 1 < n_tiles) {
            const size_t src = gsrc0 + (size_t)(t + 1) * BN * DDIM;
            cpasync16(sb + SVH + off0, g_vhi + src);
            cpasync16(sb + SVH + off1, g_vhi + src + 8);
            cpasync16(sb + SVL + off0, g_vlo + src);
            cpasync16(sb + SVL + off1, g_vlo + src + 8);
        }
        asm volatile("cp.async.commit_group;" ::: "memory");
    }

    // ---- reduce li across the quad (lanes l^1, l^2 hold the same rows) ----
    li1 += __shfl_xor_sync(0xffffffffu, li1, 1);
    li1 += __shfl_xor_sync(0xffffffffu, li1, 2);
    li2 += __shfl_xor_sync(0xffffffffu, li2, 1);
    li2 += __shfl_xor_sync(0xffffffffu, li2, 2);

    // ---- combine the two key-halves: O(partial) and li through smem ----
    __syncthreads();   // all GEMM2 smem reads done; safe to alias K buffer 0
    float* oshare = (float*)(smem + SKBUF);   // [64][64] fp32 = 16KB
    const int r1 = rowg + (lane >> 2);
    if (w_n == 1) {
        #pragma unroll
        for (int nb = 0; nb < 8; nb++) {
            int c = 8 * nb + (lane & 3) * 2;
            *(float2*)(oshare + r1 * 64 + c)       = make_float2(o[nb][0], o[nb][1]);
            *(float2*)(oshare + (r1 + 8) * 64 + c) = make_float2(o[nb][2], o[nb][3]);
        }
        if ((lane & 3) == 0) {
            s_li[r1]     = li1;
            s_li[r1 + 8] = li2;
        }
    }
    __syncthreads();

    if (w_n == 0) {
        const float lt1 = li1 + s_li[r1];
        const float lt2 = li2 + s_li[r1 + 8];
        const float inv1 = ((m0 + r1)     < len) ? (1.0f / lt1) : 0.0f;
        const float inv2 = ((m0 + r1 + 8) < len) ? (1.0f / lt2) : 0.0f;
        float* o1 = out + ((size_t)b * SEQ + m0 + r1) * (NH * DDIM) + (size_t)h * DDIM;
        float* o2 = o1 + 8 * (NH * DDIM);
        #pragma unroll
        for (int nb = 0; nb < 8; nb++) {
            int c = 8 * nb + (lane & 3) * 2;
            float2 q1 = *(const float2*)(oshare + r1 * 64 + c);
            float2 q2 = *(const float2*)(oshare + (r1 + 8) * 64 + c);
            float2 w1 = {(o[nb][0] + q1.x) * inv1, (o[nb][1] + q1.y) * inv1};
            float2 w2 = {(o[nb][2] + q2.x) * inv2, (o[nb][3] + q2.y) * inv2};
            *(float2*)(o1 + c) = w1;
            *(float2*)(o2 + c) = w2;
        }
    }
}

extern "C" void kernel_launch(void* const* d_in, const int* in_sizes, int n_in,
                              void* d_out, int out_size)
{
    const float* q    = (const float*)d_in[0];
    const float* k    = (const float*)d_in[1];
    const float* v    = (const float*)d_in[2];
    const int*   mask = (const int*)d_in[3];
    const float* bias = (const float*)d_in[4];
    float* out = (float*)d_out;

    conv_kv<<<KVELEMS / 4 / 256, 256>>>((const float4*)k, (const float4*)v);

    cudaFuncSetAttribute(attn_mma, cudaFuncAttributeMaxDynamicSharedMemorySize, SMTOT);
    dim3 grid(SEQ / BM, NH, NB);
    attn_mma<<<grid, NTH, SMTOT>>>(q, mask, bias, out);
}

// round 14
// speedup vs baseline: 1.3714x; 1.3656x over previous
#include <cuda_runtime.h>
#include <cuda_bf16.h>
#include <cstdint>

#define NB 8
#define NH 16
#define SEQ 1024
#define DDIM 64
#define BM 64
#define BN 64
#define NTH 256
#define LOG2E 1.4426950408889634f

// SMEM (96KB/CTA -> 2 CTAs/SM):
//   Q hi/lo 16KB, K triple-buffered 3x16KB (KH+KL), V double-buffered 2x16KB
#define SQH 0
#define SQL 8192
#define SKBUF 16384
#define KSTRIDE 16384
#define SVBUF 65536
#define VSTRIDE 16384
#define SMTOT 98304

#define KVELEMS (NB * NH * SEQ * DDIM)   // 8,388,608

// pre-converted K/V in bf16 hi/lo, [b,h,n,d] row-major
__device__ __nv_bfloat16 g_khi[KVELEMS];
__device__ __nv_bfloat16 g_klo[KVELEMS];
__device__ __nv_bfloat16 g_vhi[KVELEMS];
__device__ __nv_bfloat16 g_vlo[KVELEMS];

__device__ __forceinline__ uint32_t smem_u32(const void* p) {
    uint32_t a;
    asm("{ .reg .u64 t; cvta.to.shared.u64 t, %1; cvt.u32.u64 %0, t; }" : "=r"(a) : "l"(p));
    return a;
}
__device__ __forceinline__ uint32_t sw(uint32_t o) { return o ^ ((o >> 3) & 0x70); }

__device__ __forceinline__ void ldsm4(uint32_t& r0, uint32_t& r1, uint32_t& r2, uint32_t& r3,
                                      uint32_t a) {
    asm volatile("ldmatrix.sync.aligned.m8n8.x4.shared.b16 {%0,%1,%2,%3},[%4];"
                 : "=r"(r0), "=r"(r1), "=r"(r2), "=r"(r3) : "r"(a));
}
__device__ __forceinline__ void ldsm4t(uint32_t& r0, uint32_t& r1, uint32_t& r2, uint32_t& r3,
                                       uint32_t a) {
    asm volatile("ldmatrix.sync.aligned.m8n8.x4.trans.shared.b16 {%0,%1,%2,%3},[%4];"
                 : "=r"(r0), "=r"(r1), "=r"(r2), "=r"(r3) : "r"(a));
}
__device__ __forceinline__ void mma16816(float* c, uint32_t a0, uint32_t a1, uint32_t a2,
                                         uint32_t a3, uint32_t b0, uint32_t b1) {
    asm volatile("mma.sync.aligned.m16n8k16.row.col.f32.bf16.bf16.f32 "
                 "{%0,%1,%2,%3},{%4,%5,%6,%7},{%8,%9},{%0,%1,%2,%3};"
                 : "+f"(c[0]), "+f"(c[1]), "+f"(c[2]), "+f"(c[3])
                 : "r"(a0), "r"(a1), "r"(a2), "r"(a3), "r"(b0), "r"(b1));
}
// pack (x0,x1) -> bf16x2 hi part + bf16x2 residual part
__device__ __forceinline__ void split2(float x0, float x1, uint32_t& hi, uint32_t& lo) {
    uint32_t hh;
    asm("cvt.rn.bf16x2.f32 %0, %1, %2;" : "=r"(hh) : "f"(x1), "f"(x0));
    float h0 = __uint_as_float(hh << 16);
    float h1 = __uint_as_float(hh & 0xffff0000u);
    float l0 = x0 - h0, l1 = x1 - h1;
    uint32_t ll;
    asm("cvt.rn.bf16x2.f32 %0, %1, %2;" : "=r"(ll) : "f"(l1), "f"(l0));
    hi = hh; lo = ll;
}
__device__ __forceinline__ void cpasync16(uint32_t dst, const void* src) {
    asm volatile("cp.async.cg.shared.global [%0], [%1], 16;" :: "r"(dst), "l"(src));
}

// ---- prepass: convert K,V fp32 -> bf16 hi/lo, once for the whole problem ----
__global__ __launch_bounds__(256)
void conv_kv(const float4* __restrict__ k4, const float4* __restrict__ v4)
{
    const int i = blockIdx.x * 256 + threadIdx.x;   // one float4 (4 elems) each
    float4 a = k4[i];
    uint2 hi, lo;
    split2(a.x, a.y, hi.x, lo.x);
    split2(a.z, a.w, hi.y, lo.y);
    ((uint2*)g_khi)[i] = hi;
    ((uint2*)g_klo)[i] = lo;
    float4 b = v4[i];
    split2(b.x, b.y, hi.x, lo.x);
    split2(b.z, b.w, hi.y, lo.y);
    ((uint2*)g_vhi)[i] = hi;
    ((uint2*)g_vlo)[i] = lo;
}

__global__ __launch_bounds__(NTH, 2)
void attn_mma(const float* __restrict__ q, const int* __restrict__ mask,
              const float* __restrict__ bias, float* __restrict__ out)
{
    extern __shared__ char smem[];
    __shared__ int s_len;
    __shared__ float s_li[64];
    const int tid  = threadIdx.x;
    const int lane = tid & 31;
    const int w    = tid >> 5;
    const int w_m  = w & 3;        // row group: rows 16*w_m .. +15
    const int w_n  = w >> 2;       // key half: keys 32*w_n .. +31 of each tile
    const int nh   = 32 * w_n;
    const int rowg = 16 * w_m;
    const int m0   = blockIdx.x * BM;
    const int h    = blockIdx.y;
    const int b    = blockIdx.z;
    const int bh   = b * NH + h;
    const uint32_t sb = smem_u32(smem);

    // per-thread cp.async slice: this half (128 threads) loads its own 32 rows;
    // 4 threads per row, two 16B chunks per array.
    const int g    = tid & 127;                // id within the 128-thread half
    const int kr   = nh + (g >> 2);            // tile row (nh..nh+31)
    const int cc   = (g & 3) * 16;             // elem col base
    const uint32_t off0 = sw((uint32_t)kr * 128 + (uint32_t)cc * 2);
    const uint32_t off1 = sw((uint32_t)kr * 128 + (uint32_t)cc * 2 + 16);
    const size_t   gsrc0 = ((size_t)bh * SEQ + kr) * DDIM + cc;

    // ---- prologue: commit K(0), V(0), K(1) as three groups (g0,g1,g2) ----
    {
        const uint32_t dk0 = sb + SKBUF;                 // kbuf[0]
        cpasync16(dk0 + off0,        g_khi + gsrc0);
        cpasync16(dk0 + off1,        g_khi + gsrc0 + 8);
        cpasync16(dk0 + 8192 + off0, g_klo + gsrc0);
        cpasync16(dk0 + 8192 + off1, g_klo + gsrc0 + 8);
        asm volatile("cp.async.commit_group;" ::: "memory");
        const uint32_t dv0 = sb + SVBUF;                 // vbuf[0]
        cpasync16(dv0 + off0,        g_vhi + gsrc0);
        cpasync16(dv0 + off1,        g_vhi + gsrc0 + 8);
        cpasync16(dv0 + 8192 + off0, g_vlo + gsrc0);
        cpasync16(dv0 + 8192 + off1, g_vlo + gsrc0 + 8);
        asm volatile("cp.async.commit_group;" ::: "memory");
        const uint32_t dk1 = sb + SKBUF + KSTRIDE;       // kbuf[1]
        const size_t s1 = gsrc0 + (size_t)BN * DDIM;
        cpasync16(dk1 + off0,        g_khi + s1);
        cpasync16(dk1 + off1,        g_khi + s1 + 8);
        cpasync16(dk1 + 8192 + off0, g_klo + s1);
        cpasync16(dk1 + 8192 + off1, g_klo + s1 + 8);
        asm volatile("cp.async.commit_group;" ::: "memory");
    }

    if (tid == 0) s_len = 0;
    __syncthreads();
    {   // valid length (mask int32 0/1, monotone prefix)
        const int* mb = mask + (size_t)b * SEQ;
        int part = 0;
        for (int i = tid; i < SEQ; i += NTH) part += (mb[i] != 0);
        #pragma unroll
        for (int o = 16; o > 0; o >>= 1) part += __shfl_xor_sync(0xffffffffu, part, o);
        if (lane == 0) atomicAdd(&s_len, part);
    }

    // ---- Q tile fp32 -> bf16 hi/lo, swizzled [row][d] 128B rows ----
    {
        const int row  = tid >> 2;                 // 0..63
        const int colf = (tid & 3) * 16;           // float col base
        const float* qrow = q + (((size_t)bh) * SEQ + m0 + row) * DDIM + colf;
        #pragma unroll
        for (int c = 0; c < 2; c++) {              // 2 chunks of 8 floats
            float4 t0 = *(const float4*)(qrow + 8 * c);
            float4 t1 = *(const float4*)(qrow + 8 * c + 4);
            uint4 hv, lv;
            split2(t0.x, t0.y, hv.x, lv.x);
            split2(t0.z, t0.w, hv.y, lv.y);
            split2(t1.x, t1.y, hv.z, lv.z);
            split2(t1.z, t1.w, hv.w, lv.w);
            uint32_t off = sw(row * 128 + colf * 2 + 16 * c);
            *(uint4*)(smem + SQH + off) = hv;
            *(uint4*)(smem + SQL + off) = lv;
        }
    }
    __syncthreads();
    const int len = s_len;
    const int n_tiles = (len + BN - 1) / BN;

    // ldmatrix per-lane addressing pattern
    const int r8  = (lane & 7) + ((lane >> 3) & 1) * 8;
    const int c16 = ((lane >> 4) & 1) * 16;

    float o[8][4];
    #pragma unroll
    for (int i = 0; i < 8; i++)
        #pragma unroll
        for (int j = 0; j < 4; j++) o[i][j] = 0.0f;
    float li1 = 0.0f, li2 = 0.0f;

    const float* bp1 = bias + ((size_t)h * SEQ + (m0 + rowg + (lane >> 2))) * SEQ;
    const float* bp2 = bp1 + 8 * SEQ;

    // K buffer index rotates mod 3; V alternates mod 2
    int kidx = 0;

    for (int t = 0; t < n_tiles; t++) {
        const int n0 = t * BN;
        const uint32_t kvbK = sb + SKBUF + (uint32_t)kidx * KSTRIDE;
        const uint32_t kvbV = sb + SVBUF + (uint32_t)(t & 1) * VSTRIDE;

        // ---- bias prefetch (pre-scaled by log2(e); overlaps the wait) ----
        float2 bb1[4], bb2[4];
        #pragma unroll
        for (int nb = 0; nb < 4; nb++) {
            int c = n0 + nh + 8 * nb + (lane & 3) * 2;
            bb1[nb] = *(const float2*)(bp1 + c);
            bb2[nb] = *(const float2*)(bp2 + c);
            bb1[nb].x *= LOG2E; bb1[nb].y *= LOG2E;
            bb2[nb].x *= LOG2E; bb2[nb].y *= LOG2E;
        }

        // ---- K(t) must be resident; newest 2 groups {V(t), K(t+1)} may pend ----
        asm volatile("cp.async.wait_group 2;" ::: "memory");
        asm volatile("bar.sync %0, 128;" :: "r"(1 + w_n) : "memory");

        // ---- issue V(t+1) then K(t+2); WAR-safe: this half's warps all passed
        //      barrier(t), so their GEMM2(t-1)/GEMM1(t-1) reads are complete ----
        if (t + 1 < n_tiles) {
            const uint32_t dv = sb + SVBUF + (uint32_t)((t + 1) & 1) * VSTRIDE;
            const size_t src = gsrc0 + (size_t)(t + 1) * BN * DDIM;
            cpasync16(dv + off0,        g_vhi + src);
            cpasync16(dv + off1,        g_vhi + src + 8);
            cpasync16(dv + 8192 + off0, g_vlo + src);
            cpasync16(dv + 8192 + off1, g_vlo + src + 8);
        }
        asm volatile("cp.async.commit_group;" ::: "memory");
        if (t + 2 < n_tiles) {
            int k2 = kidx + 2; if (k2 >= 3) k2 -= 3;
            const uint32_t dk = sb + SKBUF + (uint32_t)k2 * KSTRIDE;
            const size_t src = gsrc0 + (size_t)(t + 2) * BN * DDIM;
            cpasync16(dk + off0,        g_khi + src);
            cpasync16(dk + off1,        g_khi + src + 8);
            cpasync16(dk + 8192 + off0, g_klo + src);
            cpasync16(dk + 8192 + off1, g_klo + src + 8);
        }
        asm volatile("cp.async.commit_group;" ::: "memory");

        // ---- GEMM1: S = QK^T over this warp's 32-key half, 3-way split ----
        float s[4][4];
        #pragma unroll
        for (int i = 0; i < 4; i++)
            #pragma unroll
            for (int j = 0; j < 4; j++) s[i][j] = 0.0f;
        #pragma unroll
        for (int kbk = 0; kbk < 4; kbk++) {
            uint32_t qoff = sw((rowg + r8) * 128 + 32 * kbk + c16);
            uint32_t a0, a1, a2, a3, e0, e1, e2, e3;
            ldsm4(a0, a1, a2, a3, sb + SQH + qoff);
            ldsm4(e0, e1, e2, e3, sb + SQL + qoff);
            #pragma unroll
            for (int nbp = 0; nbp < 2; nbp++) {
                uint32_t boff = sw((nh + 16 * nbp + r8) * 128 + 32 * kbk + c16);
                uint32_t bh0, bh1, bh2, bh3, bl0, bl1, bl2, bl3;
                ldsm4(bh0, bh1, bh2, bh3, kvbK + boff);
                ldsm4(bl0, bl1, bl2, bl3, kvbK + 8192 + boff);
                mma16816(s[2 * nbp],     a0, a1, a2, a3, bh0, bh2);
                mma16816(s[2 * nbp + 1], a0, a1, a2, a3, bh1, bh3);
                mma16816(s[2 * nbp],     e0, e1, e2, e3, bh0, bh2);
                mma16816(s[2 * nbp + 1], e0, e1, e2, e3, bh1, bh3);
                mma16816(s[2 * nbp],     a0, a1, a2, a3, bl0, bl2);
                mma16816(s[2 * nbp + 1], a0, a1, a2, a3, bl1, bl3);
            }
        }

        // ---- softmax: p = exp2(s*log2e + bias*log2e), no max-sub ----
        uint32_t pah[2][4], pal[2][4];
        #pragma unroll
        for (int nb = 0; nb < 4; nb++) {
            int n = n0 + nh + 8 * nb + (lane & 3) * 2;
            float p0 = (n     < len) ? exp2f(fmaf(s[nb][0], LOG2E, bb1[nb].x)) : 0.0f;
            float p1 = (n + 1 < len) ? exp2f(fmaf(s[nb][1], LOG2E, bb1[nb].y)) : 0.0f;
            float p2 = (n     < len) ? exp2f(fmaf(s[nb][2], LOG2E, bb2[nb].x)) : 0.0f;
            float p3 = (n + 1 < len) ? exp2f(fmaf(s[nb][3], LOG2E, bb2[nb].y)) : 0.0f;
            li1 += p0 + p1;
            li2 += p2 + p3;
            split2(p0, p1, pah[nb >> 1][(nb & 1) * 2],     pal[nb >> 1][(nb & 1) * 2]);
            split2(p2, p3, pah[nb >> 1][(nb & 1) * 2 + 1], pal[nb >> 1][(nb & 1) * 2 + 1]);
        }

        // ---- V(t) must be resident; newest 3 {K(t+1),V(t+1),K(t+2)} may pend ----
        asm volatile("cp.async.wait_group 3;" ::: "memory");
        asm volatile("bar.sync %0, 128;" :: "r"(3 + w_n) : "memory");

        // ---- GEMM2: O(partial) += P V over this warp's 32 keys ----
        #pragma unroll
        for (int kk = 0; kk < 2; kk++) {
            #pragma unroll
            for (int nbp = 0; nbp < 4; nbp++) {
                uint32_t voff = sw((nh + 16 * kk + r8) * 128 + 32 * nbp + c16);
                uint32_t vh0, vh1, vh2, vh3, vl0, vl1, vl2, vl3;
                ldsm4t(vh0, vh1, vh2, vh3, kvbV + voff);
                ldsm4t(vl0, vl1, vl2, vl3, kvbV + 8192 + voff);
                mma16816(o[2 * nbp],     pah[kk][0], pah[kk][1], pah[kk][2], pah[kk][3], vh0, vh1);
                mma16816(o[2 * nbp + 1], pah[kk][0], pah[kk][1], pah[kk][2], pah[kk][3], vh2, vh3);
                mma16816(o[2 * nbp],     pal[kk][0], pal[kk][1], pal[kk][2], pal[kk][3], vh0, vh1);
                mma16816(o[2 * nbp + 1], pal[kk][0], pal[kk][1], pal[kk][2], pal[kk][3], vh2, vh3);
                mma16816(o[2 * nbp],     pah[kk][0], pah[kk][1], pah[kk][2], pah[kk][3], vl0, vl1);
                mma16816(o[2 * nbp + 1], pah[kk][0], pah[kk][1], pah[kk][2], pah[kk][3], vl2, vl3);
            }
        }

        if (++kidx == 3) kidx = 0;
    }

    // ---- reduce li across the quad (lanes l^1, l^2 hold the same rows) ----
    li1 += __shfl_xor_sync(0xffffffffu, li1, 1);
    li1 += __shfl_xor_sync(0xffffffffu, li1, 2);
    li2 += __shfl_xor_sync(0xffffffffu, li2, 1);
    li2 += __shfl_xor_sync(0xffffffffu, li2, 2);

    // ---- combine the two key-halves: O(partial) and li through smem ----
    __syncthreads();   // all GEMM2 smem reads done; safe to alias K buffer 0
    float* oshare = (float*)(smem + SKBUF);   // [64][64] fp32 = 16KB
    const int r1 = rowg + (lane >> 2);
    if (w_n == 1) {
        #pragma unroll
        for (int nb = 0; nb < 8; nb++) {
            int c = 8 * nb + (lane & 3) * 2;
            *(float2*)(oshare + r1 * 64 + c)       = make_float2(o[nb][0], o[nb][1]);
            *(float2*)(oshare + (r1 + 8) * 64 + c) = make_float2(o[nb][2], o[nb][3]);
        }
        if ((lane & 3) == 0) {
            s_li[r1]     = li1;
            s_li[r1 + 8] = li2;
        }
    }
    __syncthreads();

    if (w_n == 0) {
        const float lt1 = li1 + s_li[r1];
        const float lt2 = li2 + s_li[r1 + 8];
        const float inv1 = ((m0 + r1)     < len) ? (1.0f / lt1) : 0.0f;
        const float inv2 = ((m0 + r1 + 8) < len) ? (1.0f / lt2) : 0.0f;
        float* o1 = out + ((size_t)b * SEQ + m0 + r1) * (NH * DDIM) + (size_t)h * DDIM;
        float* o2 = o1 + 8 * (NH * DDIM);
        #pragma unroll
        for (int nb = 0; nb < 8; nb++) {
            int c = 8 * nb + (lane & 3) * 2;
            float2 q1 = *(const float2*)(oshare + r1 * 64 + c);
            float2 q2 = *(const float2*)(oshare + (r1 + 8) * 64 + c);
            float2 w1 = {(o[nb][0] + q1.x) * inv1, (o[nb][1] + q1.y) * inv1};
            float2 w2 = {(o[nb][2] + q2.x) * inv2, (o[nb][3] + q2.y) * inv2};
            *(float2*)(o1 + c) = w1;
            *(float2*)(o2 + c) = w2;
        }
    }
}

extern "C" void kernel_launch(void* const* d_in, const int* in_sizes, int n_in,
                              void* d_out, int out_size)
{
    const float* q    = (const float*)d_in[0];
    const float* k    = (const float*)d_in[1];
    const float* v    = (const float*)d_in[2];
    const int*   mask = (const int*)d_in[3];
    const float* bias = (const float*)d_in[4];
    float* out = (float*)d_out;

    conv_kv<<<KVELEMS / 4 / 256, 256>>>((const float4*)k, (const float4*)v);

    cudaFuncSetAttribute(attn_mma, cudaFuncAttributeMaxDynamicSharedMemorySize, SMTOT);
    dim3 grid(SEQ / BM, NH, NB);
    attn_mma<<<grid, NTH, SMTOT>>>(q, mask, bias, out);
}

// round 15
// speedup vs baseline: 1.4623x; 1.0662x over previous
#include <cuda_runtime.h>
#include <cuda_bf16.h>
#include <cstdint>

#define NB 8
#define NH 16
#define SEQ 1024
#define DDIM 64
#define BM 64
#define BN 64
#define NTH 256
#define LOG2E 1.4426950408889634f

// SMEM (80KB/CTA -> 2 CTAs/SM):
//  Q hi/lo 16KB; 2 KV buffers of 32KB, each = [half0 16KB][half1 16KB],
//  half block = [KH 4K][KL 4K][VH 4K][VL 4K] (matches g_kv global layout).
#define SQH 0
#define SQL 8192
#define SBUF 16384
#define BUFSTRIDE 32768
#define HALFSTRIDE 16384
#define SMTOT 81920

// g_kv: per (bh, 32-key group): 16KB block [KH|KL|VH|VL], pre-swizzled.
// 128 bh * 32 groups * 16KB = 64MB
__device__ unsigned char g_kv[(size_t)NB * NH * 32 * 16384];

__device__ __forceinline__ uint32_t smem_u32(const void* p) {
    uint32_t a;
    asm("{ .reg .u64 t; cvta.to.shared.u64 t, %1; cvt.u32.u64 %0, t; }" : "=r"(a) : "l"(p));
    return a;
}
__device__ __forceinline__ uint32_t sw(uint32_t o) { return o ^ ((o >> 3) & 0x70); }

__device__ __forceinline__ void ldsm4(uint32_t& r0, uint32_t& r1, uint32_t& r2, uint32_t& r3,
                                      uint32_t a) {
    asm volatile("ldmatrix.sync.aligned.m8n8.x4.shared.b16 {%0,%1,%2,%3},[%4];"
                 : "=r"(r0), "=r"(r1), "=r"(r2), "=r"(r3) : "r"(a));
}
__device__ __forceinline__ void ldsm4t(uint32_t& r0, uint32_t& r1, uint32_t& r2, uint32_t& r3,
                                       uint32_t a) {
    asm volatile("ldmatrix.sync.aligned.m8n8.x4.trans.shared.b16 {%0,%1,%2,%3},[%4];"
                 : "=r"(r0), "=r"(r1), "=r"(r2), "=r"(r3) : "r"(a));
}
__device__ __forceinline__ void mma16816(float* c, uint32_t a0, uint32_t a1, uint32_t a2,
                                         uint32_t a3, uint32_t b0, uint32_t b1) {
    asm volatile("mma.sync.aligned.m16n8k16.row.col.f32.bf16.bf16.f32 "
                 "{%0,%1,%2,%3},{%4,%5,%6,%7},{%8,%9},{%0,%1,%2,%3};"
                 : "+f"(c[0]), "+f"(c[1]), "+f"(c[2]), "+f"(c[3])
                 : "r"(a0), "r"(a1), "r"(a2), "r"(a3), "r"(b0), "r"(b1));
}
__device__ __forceinline__ void split2(float x0, float x1, uint32_t& hi, uint32_t& lo) {
    uint32_t hh;
    asm("cvt.rn.bf16x2.f32 %0, %1, %2;" : "=r"(hh) : "f"(x1), "f"(x0));
    float h0 = __uint_as_float(hh << 16);
    float h1 = __uint_as_float(hh & 0xffff0000u);
    float l0 = x0 - h0, l1 = x1 - h1;
    uint32_t ll;
    asm("cvt.rn.bf16x2.f32 %0, %1, %2;" : "=r"(ll) : "f"(l1), "f"(l0));
    hi = hh; lo = ll;
}
__device__ __forceinline__ void mbar_init(uint32_t mb, uint32_t cnt) {
    asm volatile("mbarrier.init.shared.b64 [%0], %1;" :: "r"(mb), "r"(cnt) : "memory");
}
__device__ __forceinline__ void mbar_arrive(uint32_t mb) {
    asm volatile("mbarrier.arrive.shared.b64 _, [%0];" :: "r"(mb) : "memory");
}
__device__ __forceinline__ void mbar_expect_tx(uint32_t mb, uint32_t bytes) {
    asm volatile("mbarrier.arrive.expect_tx.shared.b64 _, [%0], %1;"
                 :: "r"(mb), "r"(bytes) : "memory");
}
__device__ __forceinline__ void bulk_ld(uint32_t dst, const void* src, uint32_t bytes,
                                        uint32_t mb) {
    asm volatile("cp.async.bulk.shared::cta.global.mbarrier::complete_tx::bytes "
                 "[%0], [%1], %2, [%3];"
                 :: "r"(dst), "l"(src), "r"(bytes), "r"(mb) : "memory");
}
__device__ __forceinline__ void mbar_wait(uint32_t mb, uint32_t ph) {
    asm volatile(
        "{\n\t.reg .pred P1;\n\t"
        "W%=:\n\t"
        "mbarrier.try_wait.parity.acquire.cta.shared::cta.b64 P1, [%0], %1, 0x989680;\n\t"
        "@P1 bra.uni D%=;\n\t"
        "bra.uni W%=;\n\t"
        "D%=:\n\t}"
        :: "r"(mb), "r"(ph) : "memory");
}

// ---- prepass: K,V fp32 -> bf16 hi/lo, pre-swizzled blocked layout ----
__global__ __launch_bounds__(256)
void conv_kv(const float4* __restrict__ k4, const float4* __restrict__ v4)
{
    const int i = blockIdx.x * 256 + threadIdx.x;   // one float4 each
    const int e   = i << 2;
    const int bh  = e >> 16;            // / (SEQ*DDIM)
    const int rem = e & 65535;
    const int n   = rem >> 6;
    const int d   = rem & 63;
    unsigned char* blk = g_kv + ((size_t)(bh * 32 + (n >> 5)) << 14);
    const uint32_t off = sw((uint32_t)(n & 31) * 128 + (uint32_t)d * 2);
    float4 a = k4[i];
    uint2 hi, lo;
    split2(a.x, a.y, hi.x, lo.x);
    split2(a.z, a.w, hi.y, lo.y);
    *(uint2*)(blk + off)         = hi;
    *(uint2*)(blk + 4096 + off)  = lo;
    float4 b = v4[i];
    split2(b.x, b.y, hi.x, lo.x);
    split2(b.z, b.w, hi.y, lo.y);
    *(uint2*)(blk + 8192 + off)  = hi;
    *(uint2*)(blk + 12288 + off) = lo;
}

__global__ __launch_bounds__(NTH, 2)
void attn_mma(const float* __restrict__ q, const int* __restrict__ mask,
              const float* __restrict__ bias, float* __restrict__ out)
{
    extern __shared__ char smem[];
    __shared__ int s_len;
    __shared__ float s_li[64];
    __shared__ __align__(8) unsigned long long mbf[2][2];  // full  [half][buf], cnt 1
    __shared__ __align__(8) unsigned long long mbe[2][2];  // empty [half][buf], cnt 128
    const int tid  = threadIdx.x;
    const int lane = tid & 31;
    const int w    = tid >> 5;
    const int w_m  = w & 3;
    const int w_n  = w >> 2;        // key half: keys 32*w_n..+31 of each tile
    const int nh   = 32 * w_n;
    const int rowg = 16 * w_m;
    const int m0   = blockIdx.x * BM;
    const int h    = blockIdx.y;
    const int b    = blockIdx.z;
    const int bh   = b * NH + h;
    const uint32_t sb = smem_u32(smem);

    const uint32_t mbf_a[2] = { smem_u32(&mbf[w_n][0]), smem_u32(&mbf[w_n][1]) };
    const uint32_t mbe_a[2] = { smem_u32(&mbe[w_n][0]), smem_u32(&mbe[w_n][1]) };
    const unsigned char* gsrc = g_kv + ((size_t)(bh * 32 + w_n) << 14);  // +32KB per tile

    if (tid == 0) {
        s_len = 0;
        #pragma unroll
        for (int hh = 0; hh < 2; hh++)
            #pragma unroll
            for (int bb = 0; bb < 2; bb++) {
                mbar_init(smem_u32(&mbf[hh][bb]), 1);
                mbar_init(smem_u32(&mbe[hh][bb]), 128);
            }
    }
    __syncthreads();

    // ---- prologue: elected thread per half bulk-loads tiles 0 and 1 ----
    if ((tid & 127) == 0) {
        #pragma unroll
        for (int tt = 0; tt < 2; tt++) {
            uint32_t dst = sb + SBUF + (uint32_t)tt * BUFSTRIDE + (uint32_t)w_n * HALFSTRIDE;
            mbar_expect_tx(mbf_a[tt], 16384);
            bulk_ld(dst, gsrc + (size_t)tt * 32768, 16384, mbf_a[tt]);
        }
    }

    {   // valid length (mask int32 0/1, monotone prefix)
        const int* mb = mask + (size_t)b * SEQ;
        int part = 0;
        for (int i = tid; i < SEQ; i += NTH) part += (mb[i] != 0);
        #pragma unroll
        for (int o = 16; o > 0; o >>= 1) part += __shfl_xor_sync(0xffffffffu, part, o);
        if (lane == 0) atomicAdd(&s_len, part);
    }

    // ---- Q tile fp32 -> bf16 hi/lo, swizzled [row][d] 128B rows ----
    {
        const int row  = tid >> 2;                 // 0..63
        const int colf = (tid & 3) * 16;
        const float* qrow = q + (((size_t)bh) * SEQ + m0 + row) * DDIM + colf;
        #pragma unroll
        for (int c = 0; c < 2; c++) {
            float4 t0 = *(const float4*)(qrow + 8 * c);
            float4 t1 = *(const float4*)(qrow + 8 * c + 4);
            uint4 hv, lv;
            split2(t0.x, t0.y, hv.x, lv.x);
            split2(t0.z, t0.w, hv.y, lv.y);
            split2(t1.x, t1.y, hv.z, lv.z);
            split2(t1.z, t1.w, hv.w, lv.w);
            uint32_t off = sw(row * 128 + colf * 2 + 16 * c);
            *(uint4*)(smem + SQH + off) = hv;
            *(uint4*)(smem + SQL + off) = lv;
        }
    }
    __syncthreads();
    const int len = s_len;
    const int n_tiles = (len + BN - 1) / BN;

    const int r8  = (lane & 7) + ((lane >> 3) & 1) * 8;
    const int c16 = ((lane >> 4) & 1) * 16;

    float o[8][4];
    #pragma unroll
    for (int i = 0; i < 8; i++)
        #pragma unroll
        for (int j = 0; j < 4; j++) o[i][j] = 0.0f;
    float li1 = 0.0f, li2 = 0.0f;

    const float* bp1 = bias + ((size_t)h * SEQ + (m0 + rowg + (lane >> 2))) * SEQ;
    const float* bp2 = bp1 + 8 * SEQ;

    for (int t = 0; t < n_tiles; t++) {
        const int n0 = t * BN;
        const int buf = t & 1;
        const uint32_t ph = (uint32_t)((t >> 1) & 1);
        const uint32_t khalf = sb + SBUF + (uint32_t)buf * BUFSTRIDE + (uint32_t)w_n * HALFSTRIDE;

        // ---- bias prefetch (pre-scaled by log2(e)) ----
        float2 bb1[4], bb2[4];
        #pragma unroll
        for (int nb = 0; nb < 4; nb++) {
            int c = n0 + nh + 8 * nb + (lane & 3) * 2;
            bb1[nb] = *(const float2*)(bp1 + c);
            bb2[nb] = *(const float2*)(bp2 + c);
            bb1[nb].x *= LOG2E; bb1[nb].y *= LOG2E;
            bb2[nb].x *= LOG2E; bb2[nb].y *= LOG2E;
        }

        // ---- data(t) ready? (acquire: TMA writes visible to this thread) ----
        mbar_wait(mbf_a[buf], ph);

        // ---- GEMM1: S = QK^T over this warp's 32-key half, 3-way split ----
        float s[4][4];
        #pragma unroll
        for (int i = 0; i < 4; i++)
            #pragma unroll
            for (int j = 0; j < 4; j++) s[i][j] = 0.0f;
        #pragma unroll
        for (int kbk = 0; kbk < 4; kbk++) {
            uint32_t qoff = sw((rowg + r8) * 128 + 32 * kbk + c16);
            uint32_t a0, a1, a2, a3, e0, e1, e2, e3;
            ldsm4(a0, a1, a2, a3, sb + SQH + qoff);
            ldsm4(e0, e1, e2, e3, sb + SQL + qoff);
            #pragma unroll
            for (int nbp = 0; nbp < 2; nbp++) {
                uint32_t boff = sw((16 * nbp + r8) * 128 + 32 * kbk + c16);
                uint32_t bh0, bh1, bh2, bh3, bl0, bl1, bl2, bl3;
                ldsm4(bh0, bh1, bh2, bh3, khalf + boff);
                ldsm4(bl0, bl1, bl2, bl3, khalf + 4096 + boff);
                mma16816(s[2 * nbp],     a0, a1, a2, a3, bh0, bh2);
                mma16816(s[2 * nbp + 1], a0, a1, a2, a3, bh1, bh3);
                mma16816(s[2 * nbp],     e0, e1, e2, e3, bh0, bh2);
                mma16816(s[2 * nbp + 1], e0, e1, e2, e3, bh1, bh3);
                mma16816(s[2 * nbp],     a0, a1, a2, a3, bl0, bl2);
                mma16816(s[2 * nbp + 1], a0, a1, a2, a3, bl1, bl3);
            }
        }

        // ---- softmax: p = exp2(s*log2e + bias*log2e), no max-sub ----
        uint32_t pah[2][4], pal[2][4];
        #pragma unroll
        for (int nb = 0; nb < 4; nb++) {
            int n = n0 + nh + 8 * nb + (lane & 3) * 2;
            float p0 = (n     < len) ? exp2f(fmaf(s[nb][0], LOG2E, bb1[nb].x)) : 0.0f;
            float p1 = (n + 1 < len) ? exp2f(fmaf(s[nb][1], LOG2E, bb1[nb].y)) : 0.0f;
            float p2 = (n     < len) ? exp2f(fmaf(s[nb][2], LOG2E, bb2[nb].x)) : 0.0f;
            float p3 = (n + 1 < len) ? exp2f(fmaf(s[nb][3], LOG2E, bb2[nb].y)) : 0.0f;
            li1 += p0 + p1;
            li2 += p2 + p3;
            split2(p0, p1, pah[nb >> 1][(nb & 1) * 2],     pal[nb >> 1][(nb & 1) * 2]);
            split2(p2, p3, pah[nb >> 1][(nb & 1) * 2 + 1], pal[nb >> 1][(nb & 1) * 2 + 1]);
        }

        // ---- GEMM2: O(partial) += P V over this warp's 32 keys ----
        const uint32_t vh_ = khalf + 8192;
        const uint32_t vl_ = khalf + 12288;
        #pragma unroll
        for (int kk = 0; kk < 2; kk++) {
            #pragma unroll
            for (int nbp = 0; nbp < 4; nbp++) {
                uint32_t voff = sw((16 * kk + r8) * 128 + 32 * nbp + c16);
                uint32_t vh0, vh1, vh2, vh3, vl0, vl1, vl2, vl3;
                ldsm4t(vh0, vh1, vh2, vh3, vh_ + voff);
                ldsm4t(vl0, vl1, vl2, vl3, vl_ + voff);
                mma16816(o[2 * nbp],     pah[kk][0], pah[kk][1], pah[kk][2], pah[kk][3], vh0, vh1);
                mma16816(o[2 * nbp + 1], pah[kk][0], pah[kk][1], pah[kk][2], pah[kk][3], vh2, vh3);
                mma16816(o[2 * nbp],     pal[kk][0], pal[kk][1], pal[kk][2], pal[kk][3], vh0, vh1);
                mma16816(o[2 * nbp + 1], pal[kk][0], pal[kk][1], pal[kk][2], pal[kk][3], vh2, vh3);
                mma16816(o[2 * nbp],     pah[kk][0], pah[kk][1], pah[kk][2], pah[kk][3], vl0, vl1);
                mma16816(o[2 * nbp + 1], pah[kk][0], pah[kk][1], pah[kk][2], pah[kk][3], vl2, vl3);
            }
        }

        // ---- signal buffer free; elected refills it with tile t+2 ----
        mbar_arrive(mbe_a[buf]);
        if ((tid & 127) == 0 && t + 2 < n_tiles) {
            mbar_wait(mbe_a[buf], ph);   // all 128 of this half done reading
            uint32_t dst = sb + SBUF + (uint32_t)buf * BUFSTRIDE + (uint32_t)w_n * HALFSTRIDE;
            mbar_expect_tx(mbf_a[buf], 16384);
            bulk_ld(dst, gsrc + (size_t)(t + 2) * 32768, 16384, mbf_a[buf]);
        }
    }

    // ---- reduce li across the quad (lanes l^1, l^2 hold the same rows) ----
    li1 += __shfl_xor_sync(0xffffffffu, li1, 1);
    li1 += __shfl_xor_sync(0xffffffffu, li1, 2);
    li2 += __shfl_xor_sync(0xffffffffu, li2, 1);
    li2 += __shfl_xor_sync(0xffffffffu, li2, 2);

    // ---- combine the two key-halves through smem ----
    __syncthreads();   // all warps past their loop; safe to alias buffer space
    float* oshare = (float*)(smem + SBUF);   // [64][64] fp32 = 16KB
    const int r1 = rowg + (lane >> 2);
    if (w_n == 1) {
        #pragma unroll
        for (int nb = 0; nb < 8; nb++) {
            int c = 8 * nb + (lane & 3) * 2;
            *(float2*)(oshare + r1 * 64 + c)       = make_float2(o[nb][0], o[nb][1]);
            *(float2*)(oshare + (r1 + 8) * 64 + c) = make_float2(o[nb][2], o[nb][3]);
        }
        if ((lane & 3) == 0) {
            s_li[r1]     = li1;
            s_li[r1 + 8] = li2;
        }
    }
    __syncthreads();

    if (w_n == 0) {
        const float lt1 = li1 + s_li[r1];
        const float lt2 = li2 + s_li[r1 + 8];
        const float inv1 = ((m0 + r1)     < len) ? (1.0f / lt1) : 0.0f;
        const float inv2 = ((m0 + r1 + 8) < len) ? (1.0f / lt2) : 0.0f;
        float* o1 = out + ((size_t)b * SEQ + m0 + r1) * (NH * DDIM) + (size_t)h * DDIM;
        float* o2 = o1 + 8 * (NH * DDIM);
        #pragma unroll
        for (int nb = 0; nb < 8; nb++) {
            int c = 8 * nb + (lane & 3) * 2;
            float2 q1 = *(const float2*)(oshare + r1 * 64 + c);
            float2 q2 = *(const float2*)(oshare + (r1 + 8) * 64 + c);
            float2 w1 = {(o[nb][0] + q1.x) * inv1, (o[nb][1] + q1.y) * inv1};
            float2 w2 = {(o[nb][2] + q2.x) * inv2, (o[nb][3] + q2.y) * inv2};
            *(float2*)(o1 + c) = w1;
            *(float2*)(o2 + c) = w2;
        }
    }
}

extern "C" void kernel_launch(void* const* d_in, const int* in_sizes, int n_in,
                              void* d_out, int out_size)
{
    const float* q    = (const float*)d_in[0];
    const float* k    = (const float*)d_in[1];
    const float* v    = (const float*)d_in[2];
    const int*   mask = (const int*)d_in[3];
    const float* bias = (const float*)d_in[4];
    float* out = (float*)d_out;

    conv_kv<<<(NB * NH * SEQ * DDIM) / 4 / 256, 256>>>((const float4*)k, (const float4*)v);

    cudaFuncSetAttribute(attn_mma, cudaFuncAttributeMaxDynamicSharedMemorySize, SMTOT);
    dim3 grid(SEQ / BM, NH, NB);
    attn_mma<<<grid, NTH, SMTOT>>>(q, mask, bias, out);
}